// round 17
// baseline (speedup 1.0000x reference)
#include <cuda_runtime.h>

// Problem constants
#define BB   256
#define TT   2048
#define INP  64
#define HH   32
#define NCLS 5

// ---------------- scratch (no dynamic alloc allowed) ----------------
__device__ float d_GX[(size_t)BB * TT * 128];  // W_ih[:, :64]@x_t + b_ih + b_hh, layout [b*T+t][128]
__device__ float d_P[128 * NCLS];              // W_ih[:, 64:] @ emb[n]^T per gate-row

// Packed 2-wide fp32 FMA (Blackwell FFMA2 via PTX fma.rn.f32x2)
__device__ __forceinline__ unsigned long long fma2(unsigned long long a,
                                                   unsigned long long b,
                                                   unsigned long long c) {
    unsigned long long d;
    asm("fma.rn.f32x2 %0, %1, %2, %3;" : "=l"(d) : "l"(a), "l"(b), "l"(c));
    return d;
}
__device__ __forceinline__ float2 unpack2(unsigned long long v) {
    float2 r;
    asm("mov.b64 {%0, %1}, %2;" : "=f"(r.x), "=f"(r.y) : "l"(v));
    return r;
}
// Select with a == -1 -> 0.0f (used as the t=0 "prev = 0" sentinel)
__device__ __forceinline__ float sel5z(int a, float f0, float f1, float f2, float f3, float f4) {
    float r = 0.0f;
    r = (a == 0) ? f0 : r;
    r = (a == 1) ? f1 : r;
    r = (a == 2) ? f2 : r;
    r = (a == 3) ? f3 : r;
    r = (a == 4) ? f4 : r;
    return r;
}
__device__ __forceinline__ float sel5(int a, float f0, float f1, float f2, float f3, float f4) {
    float r = f0;
    r = (a == 1) ? f1 : r;
    r = (a == 2) ? f2 : r;
    r = (a == 3) ? f3 : r;
    r = (a == 4) ? f4 : r;
    return r;
}
// Fast-but-tight activations (identical to the passing kernel; rel err ~2^-21)
__device__ __forceinline__ float fsigmoid(float x) {
    return __fdividef(1.0f, 1.0f + __expf(-x));
}
__device__ __forceinline__ float ftanh_tight(float x) {
    return __fdividef(2.0f, 1.0f + __expf(-2.0f * x)) - 1.0f;
}

// ---------------- prepass 1: P[r][n] = W_ih[r, 64:128] . emb[n] ----------------
// grid = NCLS blocks of 128 threads (block n handles class n, thread r = gate row)
__global__ void p_kernel(const float* __restrict__ Wih, const float* __restrict__ emb) {
    const int n = blockIdx.x;
    const int r = threadIdx.x;
    __shared__ __align__(16) float se[INP];
    if (r < 16)
        reinterpret_cast<float4*>(se)[r] = reinterpret_cast<const float4*>(emb + n * INP)[r];
    __syncthreads();
    float a = 0.f;
    #pragma unroll
    for (int k = 0; k < INP; k++)
        a += Wih[r * 128 + 64 + k] * se[k];
    d_P[r * NCLS + n] = a;
}

// ---------------- prepass 2: GX = x @ W_ih[:, :64]^T + (b_ih + b_hh) ----------------
#define GX_CHUNK 64
__global__ void __launch_bounds__(128) gx_kernel(
    const float* __restrict__ x, const float* __restrict__ Wih,
    const float* __restrict__ bih, const float* __restrict__ bhh)
{
    const int r = threadIdx.x;  // gate row 0..127
    const size_t base = (size_t)blockIdx.x * GX_CHUNK;  // first bt of this CTA

    // W_ih row r, columns 0..63 (x part) as 32 packed pairs
    unsigned long long w[32];
    {
        const ulonglong2* p = reinterpret_cast<const ulonglong2*>(Wih + r * 128);
        #pragma unroll
        for (int i = 0; i < 16; i++) {
            ulonglong2 u = p[i];
            w[2 * i] = u.x; w[2 * i + 1] = u.y;
        }
    }
    const float br = bih[r] + bhh[r];

    __shared__ __align__(16) float sx[2][INP];

    if (r < 16)
        reinterpret_cast<float4*>(sx[0])[r] =
            reinterpret_cast<const float4*>(x + base * INP)[r];
    __syncthreads();

    #pragma unroll 1
    for (int p = 0; p < GX_CHUNK; p++) {
        if (r < 16 && (p + 1) < GX_CHUNK)
            reinterpret_cast<float4*>(sx[(p + 1) & 1])[r] =
                reinterpret_cast<const float4*>(x + (base + p + 1) * INP)[r];

        const ulonglong2* v2 = reinterpret_cast<const ulonglong2*>(sx[p & 1]);
        unsigned long long a0 = 0ull, a1 = 0ull, a2 = 0ull, a3 = 0ull;
        #pragma unroll
        for (int m = 0; m < 16; m++) {
            ulonglong2 u = v2[m];
            if (m & 1) { a2 = fma2(w[2 * m], u.x, a2); a3 = fma2(w[2 * m + 1], u.y, a3); }
            else       { a0 = fma2(w[2 * m], u.x, a0); a1 = fma2(w[2 * m + 1], u.y, a1); }
        }
        float2 f0 = unpack2(a0), f1 = unpack2(a1), f2 = unpack2(a2), f3 = unpack2(a3);
        d_GX[(base + p) * 128 + r] = br + ((f0.x + f0.y) + (f1.x + f1.y))
                                        + ((f2.x + f2.y) + (f3.x + f3.y));
        __syncthreads();
    }
}

// ---------------- recurrent kernel: one CTA (2 warps) per batch row ----------------
// warp0: gates i (row j), f (row 32+j); owns c, computes h, publishes h.
// warp1: gates g (row 64+j), o (row 96+j); publishes activated g,o; emits log-softmax output.
// Both warps run the 5-logit butterfly on h(t) redundantly -> amax stays register-local.
__global__ void __launch_bounds__(64, 1) ar_rec_kernel(
    const float* __restrict__ Whh,  // [128, 32]
    const float* __restrict__ Wfc,  // [5, 32]
    const float* __restrict__ bfc,  // [5]
    float* __restrict__ out)        // [B, T, 5]
{
    const int w = threadIdx.x >> 5;
    const int j = threadIdx.x & 31;
    const int b = blockIdx.x;

    __shared__ __align__(16) float s_h[32];
    __shared__ float s_go[2][32];

    const int r0 = w * 64 + j;       // i-row (w0) / g-row (w1)
    const int r1 = w * 64 + 32 + j;  // f-row (w0) / o-row (w1)

    // W_hh rows for this lane's 2 gate rows, packed pairs
    unsigned long long wh0[16], wh1[16];
    {
        const ulonglong2* q0 = reinterpret_cast<const ulonglong2*>(Whh + r0 * HH);
        const ulonglong2* q1 = reinterpret_cast<const ulonglong2*>(Whh + r1 * HH);
        #pragma unroll
        for (int i = 0; i < 8; i++) {
            ulonglong2 u0 = q0[i], u1 = q1[i];
            wh0[2 * i] = u0.x; wh0[2 * i + 1] = u0.y;
            wh1[2 * i] = u1.x; wh1[2 * i + 1] = u1.y;
        }
    }
    float wfc_[NCLS], bf[NCLS];
    #pragma unroll
    for (int n = 0; n < NCLS; n++) { wfc_[n] = Wfc[n * HH + j]; bf[n] = bfc[n]; }

    float P0[NCLS], P1[NCLS];
    #pragma unroll
    for (int n = 0; n < NCLS; n++) {
        P0[n] = d_P[r0 * NCLS + n];
        P1[n] = d_P[r1 * NCLS + n];
    }

    float c = 0.f, h = 0.f;
    if (w == 0) s_h[j] = 0.f;
    int am = -1;  // sentinel: prev(-1) = 0  ->  psel = 0

    const float* gxp = d_GX + (size_t)b * TT * 128;
    float gx0_c, gx1_c, gx0_n1, gx1_n1, gx0_n2, gx1_n2;
    gx0_c  = __ldg(gxp + r0);        gx1_c  = __ldg(gxp + r1);
    gx0_n1 = __ldg(gxp + 128 + r0);  gx1_n1 = __ldg(gxp + 128 + r1);

    float* op = out + (size_t)b * TT * NCLS;
    __syncthreads();

    #pragma unroll 1
    for (int t = 0; t < TT; t++) {
        // prefetch GX for t+2 (two-step slack covers DRAM/L2 latency)
        const int tp = (t + 2 < TT) ? t + 2 : TT - 1;
        gx0_n2 = __ldg(gxp + (size_t)tp * 128 + r0);
        gx1_n2 = __ldg(gxp + (size_t)tp * 128 + r1);

        // ---- W_hh . h(t-1): 2 gate dots per lane, packed, weights in registers ----
        const ulonglong2* hv = reinterpret_cast<const ulonglong2*>(s_h);
        unsigned long long a00 = 0ull, a01 = 0ull, a10 = 0ull, a11 = 0ull;
        #pragma unroll
        for (int m = 0; m < 8; m++) {
            ulonglong2 u = hv[m];  // broadcast LDS.128
            a00 = fma2(wh0[2 * m],     u.x, a00);
            a01 = fma2(wh0[2 * m + 1], u.y, a01);
            a10 = fma2(wh1[2 * m],     u.x, a10);
            a11 = fma2(wh1[2 * m + 1], u.y, a11);
        }
        float2 f00 = unpack2(a00), f01 = unpack2(a01), f10 = unpack2(a10), f11 = unpack2(a11);
        float d0 = (f00.x + f00.y) + (f01.x + f01.y);
        float d1 = (f10.x + f10.y) + (f11.x + f11.y);

        float raw0 = gx0_c + sel5z(am, P0[0], P0[1], P0[2], P0[3], P0[4]) + d0;
        float raw1 = gx1_c + sel5z(am, P1[0], P1[1], P1[2], P1[3], P1[4]) + d1;

        float iv = 0.f, fv = 0.f;
        if (w == 1) {
            float gv = ftanh_tight(raw0);   // g gate
            float ov = fsigmoid(raw1);      // o gate
            s_go[0][j] = gv;
            s_go[1][j] = ov;
        } else {
            iv = fsigmoid(raw0);            // i gate
            fv = fsigmoid(raw1);            // f gate
        }
        __syncthreads();  // bar1: g,o acts published

        if (w == 0) {
            float gv = s_go[0][j];
            float ov = s_go[1][j];
            c = fv * c + iv * gv;
            h = ov * ftanh_tight(c);
            s_h[j] = h;
        }
        __syncthreads();  // bar2: h(t) published

        // ---- butterfly on h(t): both warps, bit-identical -> same amax ----
        const float hj = (w == 0) ? h : s_h[j];
        float p0 = wfc_[0] * hj, p1 = wfc_[1] * hj, p2 = wfc_[2] * hj,
              p3 = wfc_[3] * hj, p4 = wfc_[4] * hj;
        #pragma unroll
        for (int off = 16; off > 0; off >>= 1) {
            p0 += __shfl_xor_sync(0xffffffffu, p0, off);
            p1 += __shfl_xor_sync(0xffffffffu, p1, off);
            p2 += __shfl_xor_sync(0xffffffffu, p2, off);
            p3 += __shfl_xor_sync(0xffffffffu, p3, off);
            p4 += __shfl_xor_sync(0xffffffffu, p4, off);
        }
        p0 += bf[0]; p1 += bf[1]; p2 += bf[2]; p3 += bf[3]; p4 += bf[4];

        // argmax (first-max tie-break, matching jnp.argmax)
        am = 0; float best = p0;
        if (p1 > best) { best = p1; am = 1; }
        if (p2 > best) { best = p2; am = 2; }
        if (p3 > best) { best = p3; am = 3; }
        if (p4 > best) { best = p4; am = 4; }

        // ---- output logp(t): warp1 only (off warp0's recurrence path) ----
        if (w == 1) {
            float e0 = __expf(p0 - best), e1 = __expf(p1 - best), e2 = __expf(p2 - best),
                  e3 = __expf(p3 - best), e4 = __expf(p4 - best);
            float lse = best + __logf(e0 + e1 + e2 + e3 + e4);
            if (j < NCLS)
                op[(size_t)t * NCLS + j] = sel5(j, p0, p1, p2, p3, p4) - lse;
        }

        gx0_c = gx0_n1; gx1_c = gx1_n1;
        gx0_n1 = gx0_n2; gx1_n1 = gx1_n2;
    }
}

extern "C" void kernel_launch(void* const* d_in, const int* in_sizes, int n_in,
                              void* d_out, int out_size) {
    // metadata order: x, x_lengths, edge_list, W_ih, W_hh, b_ih, b_hh, W_fc, b_fc, emb
    const float* x   = (const float*)d_in[0];
    const float* Wih = (const float*)d_in[3];
    const float* Whh = (const float*)d_in[4];
    const float* bih = (const float*)d_in[5];
    const float* bhh = (const float*)d_in[6];
    const float* Wfc = (const float*)d_in[7];
    const float* bfc = (const float*)d_in[8];
    const float* emb = (const float*)d_in[9];
    float* out = (float*)d_out;

    p_kernel<<<NCLS, 128>>>(Wih, emb);
    gx_kernel<<<(BB * TT) / GX_CHUNK, 128>>>(x, Wih, bih, bhh);
    ar_rec_kernel<<<BB, 64>>>(Whh, Wfc, bfc, out);
}